// round 1
// baseline (speedup 1.0000x reference)
#include <cuda_runtime.h>
#include <math.h>

#define NB 8
#define CTC 1024
#define LLEN 1024
#define NH 16
#define NG 8

// ---------------- scratch (no allocations allowed) ----------------
__device__ float g_kbuf[NB * 512 * LLEN];     // 16MB  k: [n][h*32+d][l]
__device__ float g_qbuf[NB * 512 * LLEN];     // 16MB  q (pre-scaled by 1/32)
__device__ float g_vbuf[NB * 1024 * LLEN];    // 32MB  v: [n][h*64+d][l]
__device__ float g_t2[NB * 1024 * LLEN];      // 32MB  tokens + kqv
__device__ float g_wgT[NG * 128 * 256];       // fused+transposed qkv weights [g][k][256r]
__device__ float g_bg[NG * 256];              // fused qkv bias
__device__ float g_wfT[1024 * 1024];          // fused+transposed ff weight [k][c]
__device__ float g_bf[1024];                  // fused ff bias

// ---------------- prep: fold BN into weights, transpose ----------------
__global__ void prep_kernel(
    const float* __restrict__ kw, const float* __restrict__ kb, const float* __restrict__ kga,
    const float* __restrict__ kbe, const float* __restrict__ km, const float* __restrict__ kv,
    const float* __restrict__ qw, const float* __restrict__ qb, const float* __restrict__ qga,
    const float* __restrict__ qbe, const float* __restrict__ qm, const float* __restrict__ qv,
    const float* __restrict__ vw, const float* __restrict__ vb, const float* __restrict__ vga,
    const float* __restrict__ vbe, const float* __restrict__ vm, const float* __restrict__ vv,
    const float* __restrict__ fw, const float* __restrict__ fb, const float* __restrict__ fga,
    const float* __restrict__ fbe, const float* __restrict__ fm, const float* __restrict__ fv)
{
    int id = blockIdx.x * blockDim.x + threadIdx.x;
    if (id < 1024 * 1024) {
        int c = id & 1023, k = id >> 10;
        float inv = fga[c] * rsqrtf(fv[c] + 1e-5f);
        g_wfT[(size_t)k * 1024 + c] = fw[(size_t)c * 1024 + k] * inv;
        return;
    }
    int id2 = id - 1024 * 1024;
    if (id2 < NG * 128 * 256) {
        int r = id2 & 255;
        int k = (id2 >> 8) & 127;
        int g = id2 >> 15;
        float w;
        if (r < 64) {
            int c = g * 64 + r;
            float inv = kga[c] * rsqrtf(kv[c] + 1e-5f);
            w = kw[c * 128 + k] * inv;
        } else if (r < 128) {
            int c = g * 64 + (r - 64);
            float inv = qga[c] * rsqrtf(qv[c] + 1e-5f);
            w = qw[c * 128 + k] * inv * 0.03125f;   // fold 1/sqrt(L)=1/32 into q
        } else {
            int c = g * 128 + (r - 128);
            float inv = vga[c] * rsqrtf(vv[c] + 1e-5f);
            w = vw[c * 128 + k] * inv;
        }
        g_wgT[id2] = w;
        (void)k;
        return;
    }
    int id3 = id2 - NG * 128 * 256;
    if (id3 < NG * 256) {
        int g = id3 >> 8, r = id3 & 255;
        float bias;
        if (r < 64) {
            int c = g * 64 + r;
            float inv = kga[c] * rsqrtf(kv[c] + 1e-5f);
            bias = kb[c] * inv + kbe[c] - km[c] * inv;
        } else if (r < 128) {
            int c = g * 64 + (r - 64);
            float inv = qga[c] * rsqrtf(qv[c] + 1e-5f);
            bias = (qb[c] * inv + qbe[c] - qm[c] * inv) * 0.03125f;
        } else {
            int c = g * 128 + (r - 128);
            float inv = vga[c] * rsqrtf(vv[c] + 1e-5f);
            bias = vb[c] * inv + vbe[c] - vm[c] * inv;
        }
        g_bg[id3] = bias;
        return;
    }
    int c = id3 - NG * 256;
    if (c < 1024) {
        float inv = fga[c] * rsqrtf(fv[c] + 1e-5f);
        g_bf[c] = fb[c] * inv + fbe[c] - fm[c] * inv;
    }
}

// ---------------- shared GEMM inner: 128x128 tile, 8x8 microtile ----------------
__device__ __forceinline__ void gemm_inner32(const float* __restrict__ Ast,
                                             const float* __restrict__ Bs,
                                             float acc[8][8], int r0, int q0)
{
#pragma unroll
    for (int j = 0; j < 32; ++j) {
        float4 a0 = *(const float4*)&Ast[j * 132 + r0];
        float4 a1 = *(const float4*)&Ast[j * 132 + r0 + 4];
        float4 b0 = *(const float4*)&Bs[j * 132 + q0];
        float4 b1 = *(const float4*)&Bs[j * 132 + q0 + 4];
        float a[8] = {a0.x, a0.y, a0.z, a0.w, a1.x, a1.y, a1.z, a1.w};
        float b[8] = {b0.x, b0.y, b0.z, b0.w, b1.x, b1.y, b1.z, b1.w};
#pragma unroll
        for (int ii = 0; ii < 8; ++ii)
#pragma unroll
            for (int jj = 0; jj < 8; ++jj)
                acc[ii][jj] += a[ii] * b[jj];
    }
}

// ---------------- kernel 1: fused grouped qkv conv ----------------
__global__ __launch_bounds__(256) void qkv_conv_kernel(const float* __restrict__ tokens)
{
    __shared__ float Ast[32 * 132];
    __shared__ float Bs[32 * 132];
    int t = threadIdx.x;
    int lt = blockIdx.x;    // 0..7 (128 l each)
    int rb = blockIdx.y;    // 0..1 (128 rows each of 256)
    int ng = blockIdx.z;    // 0..63
    int n = ng >> 3, g = ng & 7;
    int l0 = lt * 128;
    int r0 = (t & 15) * 8;
    int q0 = (t >> 4) * 8;

    float acc[8][8];
#pragma unroll
    for (int i = 0; i < 8; ++i)
#pragma unroll
        for (int j = 0; j < 8; ++j) acc[i][j] = 0.f;

    for (int kc = 0; kc < 128; kc += 32) {
        if (kc) __syncthreads();
#pragma unroll
        for (int i = 0; i < 4; ++i) {
            int f4 = i * 256 + t;
            int j = f4 >> 5, c4 = (f4 & 31) * 4;
            *(float4*)&Ast[j * 132 + c4] =
                *(const float4*)&g_wgT[((g * 128) + kc + j) * 256 + rb * 128 + c4];
            *(float4*)&Bs[j * 132 + c4] =
                *(const float4*)&tokens[((size_t)(n * 1024 + g * 128 + kc + j)) * 1024 + l0 + c4];
        }
        __syncthreads();
        gemm_inner32(Ast, Bs, acc, r0, q0);
    }

#pragma unroll
    for (int ii = 0; ii < 8; ++ii) {
        int rr = rb * 128 + r0 + ii;
        float bias = g_bg[g * 256 + rr];
        float* dst;
        if (rr < 64)
            dst = g_kbuf + ((size_t)(n * 512 + g * 64 + rr)) * 1024;
        else if (rr < 128)
            dst = g_qbuf + ((size_t)(n * 512 + g * 64 + (rr - 64))) * 1024;
        else
            dst = g_vbuf + ((size_t)(n * 1024 + g * 128 + (rr - 128))) * 1024;
        float4 o0 = make_float4(acc[ii][0] + bias, acc[ii][1] + bias, acc[ii][2] + bias, acc[ii][3] + bias);
        float4 o1 = make_float4(acc[ii][4] + bias, acc[ii][5] + bias, acc[ii][6] + bias, acc[ii][7] + bias);
        *(float4*)&dst[l0 + q0] = o0;
        *(float4*)&dst[l0 + q0 + 4] = o1;
    }
}

// ---------------- kernel 2: fused flash attention + residual ----------------
// per CTA: one (n, h, q-tile of 128). K/V streamed in 128-wide tiles.
#define ATTN_SMEM_FLOATS (4096 + 4096 + 64 * 129 + 128 * 132 + 16 * 128 + 3 * 128)
__global__ __launch_bounds__(256) void attn_kernel(const float* __restrict__ tokens)
{
    extern __shared__ float sm[];
    float* Qs = sm;                  // [32][128]
    float* Ks = Qs + 4096;           // [32][128]
    float* Vs = Ks + 4096;           // [64][129]
    float* Ps = Vs + 64 * 129;       // [128][132]
    float* red = Ps + 128 * 132;     // [16][128]
    float* mbuf = red + 16 * 128;    // [128]
    float* lbuf = mbuf + 128;        // [128]
    float* facb = lbuf + 128;        // [128]

    int t = threadIdx.x;
    int qt = blockIdx.x, h = blockIdx.y, n = blockIdx.z;
    int q0g = qt * 128;
    const float* Kg = g_kbuf + ((size_t)(n * 512 + h * 32)) * 1024;
    const float* Qg = g_qbuf + ((size_t)(n * 512 + h * 32)) * 1024;
    const float* Vg = g_vbuf + ((size_t)(n * 1024 + h * 64)) * 1024;

    // load Q tile once
#pragma unroll
    for (int i = 0; i < 4; ++i) {
        int f4 = i * 256 + t;
        int d = f4 >> 5, c4 = (f4 & 31) * 4;
        *(float4*)&Qs[d * 128 + c4] = *(const float4*)&Qg[(size_t)d * 1024 + q0g + c4];
    }
    if (t < 128) { mbuf[t] = -1e30f; lbuf[t] = 0.f; }

    float o[4][8];
#pragma unroll
    for (int i = 0; i < 4; ++i)
#pragma unroll
        for (int j = 0; j < 8; ++j) o[i][j] = 0.f;

    int qx = t & 15, kgp = t >> 4;
    int sq0 = qx * 8, sk0 = kgp * 8;
    int dg = t & 15, qg = t >> 4;
    int d0 = dg * 4, oq0 = qg * 8;
    int lane = t & 31, dq = t >> 5;

    for (int kt = 0; kt < 8; ++kt) {
        int k0 = kt * 128;
        __syncthreads();
        // load K tile
#pragma unroll
        for (int i = 0; i < 4; ++i) {
            int f4 = i * 256 + t;
            int d = f4 >> 5, c4 = (f4 & 31) * 4;
            *(float4*)&Ks[d * 128 + c4] = *(const float4*)&Kg[(size_t)d * 1024 + k0 + c4];
        }
        // load V tile (pitch 129, conflict-light)
#pragma unroll
        for (int i = 0; i < 8; ++i) {
            int d = i * 8 + dq;
            const float* src = Vg + (size_t)d * 1024 + k0;
            float* dst = Vs + d * 129;
            dst[lane] = src[lane];
            dst[lane + 32] = src[lane + 32];
            dst[lane + 64] = src[lane + 64];
            dst[lane + 96] = src[lane + 96];
        }
        __syncthreads();

        // S = K^T Q  (8k x 8q per thread)
        float s[8][8];
#pragma unroll
        for (int i = 0; i < 8; ++i)
#pragma unroll
            for (int j = 0; j < 8; ++j) s[i][j] = 0.f;
#pragma unroll
        for (int d = 0; d < 32; ++d) {
            float4 ka0 = *(const float4*)&Ks[d * 128 + sk0];
            float4 ka1 = *(const float4*)&Ks[d * 128 + sk0 + 4];
            float4 qa0 = *(const float4*)&Qs[d * 128 + sq0];
            float4 qa1 = *(const float4*)&Qs[d * 128 + sq0 + 4];
            float ka[8] = {ka0.x, ka0.y, ka0.z, ka0.w, ka1.x, ka1.y, ka1.z, ka1.w};
            float qa[8] = {qa0.x, qa0.y, qa0.z, qa0.w, qa1.x, qa1.y, qa1.z, qa1.w};
#pragma unroll
            for (int i = 0; i < 8; ++i)
#pragma unroll
                for (int j = 0; j < 8; ++j) s[i][j] += ka[i] * qa[j];
        }
        // per-q partial max over this thread's 8 k
#pragma unroll
        for (int j = 0; j < 8; ++j) {
            float cm = s[0][j];
#pragma unroll
            for (int i = 1; i < 8; ++i) cm = fmaxf(cm, s[i][j]);
            red[kgp * 128 + sq0 + j] = cm;
        }
        __syncthreads();
        if (t < 128) {
            float mt = red[t];
#pragma unroll
            for (int g2 = 1; g2 < 16; ++g2) mt = fmaxf(mt, red[g2 * 128 + t]);
            float mo = mbuf[t];
            float mn = fmaxf(mo, mt);
            float f = __expf(mo - mn);
            mbuf[t] = mn;
            facb[t] = f;
            lbuf[t] *= f;
        }
        __syncthreads();
        // P = exp(S - m), write to smem + partial sums
        float mj[8];
#pragma unroll
        for (int j = 0; j < 8; ++j) mj[j] = mbuf[sq0 + j];
        float psum[8];
#pragma unroll
        for (int j = 0; j < 8; ++j) psum[j] = 0.f;
#pragma unroll
        for (int i = 0; i < 8; ++i) {
#pragma unroll
            for (int j = 0; j < 8; ++j) {
                float p = __expf(s[i][j] - mj[j]);
                s[i][j] = p;
                psum[j] += p;
            }
            float4 p0 = make_float4(s[i][0], s[i][1], s[i][2], s[i][3]);
            float4 p1 = make_float4(s[i][4], s[i][5], s[i][6], s[i][7]);
            *(float4*)&Ps[(sk0 + i) * 132 + sq0] = p0;
            *(float4*)&Ps[(sk0 + i) * 132 + sq0 + 4] = p1;
        }
#pragma unroll
        for (int j = 0; j < 8; ++j) red[kgp * 128 + sq0 + j] = psum[j];
        __syncthreads();
        if (t < 128) {
            float a = 0.f;
#pragma unroll
            for (int g2 = 0; g2 < 16; ++g2) a += red[g2 * 128 + t];
            lbuf[t] += a;
        }
        // O = O*fac + V @ P
        float fj[8];
#pragma unroll
        for (int j = 0; j < 8; ++j) fj[j] = facb[oq0 + j];
#pragma unroll
        for (int i = 0; i < 4; ++i)
#pragma unroll
            for (int j = 0; j < 8; ++j) o[i][j] *= fj[j];
#pragma unroll 4
        for (int k = 0; k < 128; ++k) {
            float4 p0 = *(const float4*)&Ps[k * 132 + oq0];
            float4 p1 = *(const float4*)&Ps[k * 132 + oq0 + 4];
            float pv[8] = {p0.x, p0.y, p0.z, p0.w, p1.x, p1.y, p1.z, p1.w};
            float v0 = Vs[(d0 + 0) * 129 + k];
            float v1 = Vs[(d0 + 1) * 129 + k];
            float v2 = Vs[(d0 + 2) * 129 + k];
            float v3 = Vs[(d0 + 3) * 129 + k];
#pragma unroll
            for (int j = 0; j < 8; ++j) {
                o[0][j] += v0 * pv[j];
                o[1][j] += v1 * pv[j];
                o[2][j] += v2 * pv[j];
                o[3][j] += v3 * pv[j];
            }
        }
    }
    __syncthreads();
    float li[8];
#pragma unroll
    for (int j = 0; j < 8; ++j) li[j] = 1.0f / lbuf[oq0 + j];
#pragma unroll
    for (int i = 0; i < 4; ++i) {
        size_t row = ((size_t)(n * 1024 + h * 64 + d0 + i)) * 1024 + q0g;
        float4 t0 = *(const float4*)&tokens[row + oq0];
        float4 t1 = *(const float4*)&tokens[row + oq0 + 4];
        float4 r0 = make_float4(t0.x + o[i][0] * li[0], t0.y + o[i][1] * li[1],
                                t0.z + o[i][2] * li[2], t0.w + o[i][3] * li[3]);
        float4 r1 = make_float4(t1.x + o[i][4] * li[4], t1.y + o[i][5] * li[5],
                                t1.z + o[i][6] * li[6], t1.w + o[i][7] * li[7]);
        *(float4*)&g_t2[row + oq0] = r0;
        *(float4*)&g_t2[row + oq0 + 4] = r1;
    }
}

// ---------------- kernel 3: ff conv (dense 1024x1024) + residual ----------------
__global__ __launch_bounds__(256) void fconv_kernel(float* __restrict__ out)
{
    __shared__ float Ast[32 * 132];
    __shared__ float Bs[32 * 132];
    int t = threadIdx.x;
    int lt = blockIdx.x, rb = blockIdx.y, n = blockIdx.z;
    int l0 = lt * 128, c0 = rb * 128;
    int r0 = (t & 15) * 8;
    int q0 = (t >> 4) * 8;

    float acc[8][8];
#pragma unroll
    for (int i = 0; i < 8; ++i)
#pragma unroll
        for (int j = 0; j < 8; ++j) acc[i][j] = 0.f;

    for (int kc = 0; kc < 1024; kc += 32) {
        if (kc) __syncthreads();
#pragma unroll
        for (int i = 0; i < 4; ++i) {
            int f4 = i * 256 + t;
            int j = f4 >> 5, c4 = (f4 & 31) * 4;
            *(float4*)&Ast[j * 132 + c4] =
                *(const float4*)&g_wfT[(size_t)(kc + j) * 1024 + c0 + c4];
            *(float4*)&Bs[j * 132 + c4] =
                *(const float4*)&g_t2[((size_t)(n * 1024 + kc + j)) * 1024 + l0 + c4];
        }
        __syncthreads();
        gemm_inner32(Ast, Bs, acc, r0, q0);
    }

#pragma unroll
    for (int ii = 0; ii < 8; ++ii) {
        int c = c0 + r0 + ii;
        float bias = g_bf[c];
        size_t row = ((size_t)(n * 1024 + c)) * 1024 + l0 + q0;
        float4 t0 = *(const float4*)&g_t2[row];
        float4 t1 = *(const float4*)&g_t2[row + 4];
        float4 o0 = make_float4(t0.x + acc[ii][0] + bias, t0.y + acc[ii][1] + bias,
                                t0.z + acc[ii][2] + bias, t0.w + acc[ii][3] + bias);
        float4 o1 = make_float4(t1.x + acc[ii][4] + bias, t1.y + acc[ii][5] + bias,
                                t1.z + acc[ii][6] + bias, t1.w + acc[ii][7] + bias);
        *(float4*)&out[row] = o0;
        *(float4*)&out[row + 4] = o1;
    }
}

// ---------------- launch ----------------
extern "C" void kernel_launch(void* const* d_in, const int* in_sizes, int n_in,
                              void* d_out, int out_size)
{
    (void)in_sizes; (void)n_in; (void)out_size;
    const float* tokens = (const float*)d_in[0];
    const float* p[24];
    for (int i = 0; i < 24; ++i) p[i] = (const float*)d_in[1 + i];

    size_t attn_smem = (size_t)ATTN_SMEM_FLOATS * sizeof(float);
    cudaFuncSetAttribute(attn_kernel, cudaFuncAttributeMaxDynamicSharedMemorySize,
                         (int)attn_smem);

    int total_prep = 1024 * 1024 + NG * 128 * 256 + NG * 256 + 1024;
    prep_kernel<<<(total_prep + 255) / 256, 256>>>(
        p[0], p[1], p[2], p[3], p[4], p[5],
        p[6], p[7], p[8], p[9], p[10], p[11],
        p[12], p[13], p[14], p[15], p[16], p[17],
        p[18], p[19], p[20], p[21], p[22], p[23]);

    qkv_conv_kernel<<<dim3(8, 2, 64), 256>>>(tokens);
    attn_kernel<<<dim3(8, 16, 8), 256, attn_smem>>>(tokens);
    fconv_kernel<<<dim3(8, 8, 8), 256>>>((float*)d_out);
}

// round 3
// speedup vs baseline: 1.8181x; 1.8181x over previous
#include <cuda_runtime.h>
#include <cstdint>
#include <math.h>

// ---------------- scratch ----------------
__device__ float g_kbuf[8 * 16 * 1024 * 32];   // [n][h][l][32d] tf32
__device__ float g_qbuf[8 * 16 * 1024 * 32];   // [n][h][l][32d] tf32 (pre-scaled 1/32)
__device__ float g_vbuf[8 * 1024 * 1024];      // [n][c][l] tf32
__device__ float g_t2 [8 * 1024 * 1024];       // [n][c][l] fp32 (attn + residual)
__device__ float g_t2T[8 * 1024 * 1024];       // [n][l][c] tf32
__device__ float g_tokT[8 * 1024 * 1024];      // [n][l][c] tf32
__device__ float g_wg[8 * 256 * 128];          // [g][r][k] tf32
__device__ float g_bg[8 * 256];
__device__ float g_wf[1024 * 1024];            // [c][k] tf32
__device__ float g_bf[1024];

// ---------------- helpers ----------------
__device__ __forceinline__ uint32_t smem_u32(const void* p) {
    uint32_t a;
    asm("{ .reg .u64 t; cvta.to.shared.u64 t, %1; cvt.u32.u64 %0, t; }" : "=r"(a) : "l"(p));
    return a;
}
__device__ __forceinline__ float f2tf(float x) {
    uint32_t r;
    asm("cvt.rna.tf32.f32 %0, %1;" : "=r"(r) : "f"(x));
    return __uint_as_float(r);
}
#define CPA(dst, src) asm volatile("cp.async.cg.shared.global [%0], [%1], 16;" :: "r"(dst), "l"(__cvta_generic_to_global(src)))
#define CPC()  asm volatile("cp.async.commit_group;" ::: "memory")
#define CPW0() asm volatile("cp.async.wait_group 0;" ::: "memory")

__device__ __forceinline__ void mma8(float* d, const uint32_t* a, const uint32_t* b) {
    asm volatile(
        "mma.sync.aligned.m16n8k8.row.col.f32.tf32.tf32.f32 "
        "{%0,%1,%2,%3}, {%4,%5,%6,%7}, {%8,%9}, {%0,%1,%2,%3};"
        : "+f"(d[0]), "+f"(d[1]), "+f"(d[2]), "+f"(d[3])
        : "r"(a[0]), "r"(a[1]), "r"(a[2]), "r"(a[3]), "r"(b[0]), "r"(b[1]));
}

// ---------------- prep: fold BN, tf32-round weights ----------------
__global__ void prep_kernel(
    const float* __restrict__ kw, const float* __restrict__ kb, const float* __restrict__ kga,
    const float* __restrict__ kbe, const float* __restrict__ km, const float* __restrict__ kv,
    const float* __restrict__ qw, const float* __restrict__ qb, const float* __restrict__ qga,
    const float* __restrict__ qbe, const float* __restrict__ qm, const float* __restrict__ qv,
    const float* __restrict__ vw, const float* __restrict__ vb, const float* __restrict__ vga,
    const float* __restrict__ vbe, const float* __restrict__ vm, const float* __restrict__ vv,
    const float* __restrict__ fw, const float* __restrict__ fb, const float* __restrict__ fga,
    const float* __restrict__ fbe, const float* __restrict__ fm, const float* __restrict__ fv)
{
    int id = blockIdx.x * blockDim.x + threadIdx.x;
    if (id < 1024 * 1024) {
        int c = id >> 10;
        float inv = fga[c] * rsqrtf(fv[c] + 1e-5f);
        g_wf[id] = f2tf(fw[id] * inv);
        return;
    }
    int id2 = id - 1024 * 1024;
    if (id2 < 8 * 256 * 128) {
        int k = id2 & 127;
        int r = (id2 >> 7) & 255;
        int g = id2 >> 15;
        float w;
        if (r < 64) {
            int c = g * 64 + r;
            float inv = kga[c] * rsqrtf(kv[c] + 1e-5f);
            w = kw[c * 128 + k] * inv;
        } else if (r < 128) {
            int c = g * 64 + (r - 64);
            float inv = qga[c] * rsqrtf(qv[c] + 1e-5f);
            w = qw[c * 128 + k] * inv * 0.03125f;
        } else {
            int c = g * 128 + (r - 128);
            float inv = vga[c] * rsqrtf(vv[c] + 1e-5f);
            w = vw[c * 128 + k] * inv;
        }
        g_wg[id2] = f2tf(w);
        return;
    }
    int id3 = id2 - 8 * 256 * 128;
    if (id3 < 8 * 256) {
        int g = id3 >> 8, r = id3 & 255;
        float bias;
        if (r < 64) {
            int c = g * 64 + r;
            float inv = kga[c] * rsqrtf(kv[c] + 1e-5f);
            bias = kb[c] * inv + kbe[c] - km[c] * inv;
        } else if (r < 128) {
            int c = g * 64 + (r - 64);
            float inv = qga[c] * rsqrtf(qv[c] + 1e-5f);
            bias = (qb[c] * inv + qbe[c] - qm[c] * inv) * 0.03125f;
        } else {
            int c = g * 128 + (r - 128);
            float inv = vga[c] * rsqrtf(vv[c] + 1e-5f);
            bias = vb[c] * inv + vbe[c] - vm[c] * inv;
        }
        g_bg[id3] = bias;
        return;
    }
    int c = id3 - 8 * 256;
    if (c < 1024) {
        float inv = fga[c] * rsqrtf(fv[c] + 1e-5f);
        g_bf[c] = fb[c] * inv + fbe[c] - fm[c] * inv;
    }
}

// ---------------- tokens transpose: [n][c][l] -> [n][l][c], tf32 ----------------
__global__ __launch_bounds__(256) void transpose_kernel(const float* __restrict__ tokens)
{
    __shared__ float tile[32][33];
    int l0 = blockIdx.x * 32, c0 = blockIdx.y * 32, n = blockIdx.z;
    int t = threadIdx.x;
#pragma unroll
    for (int i = 0; i < 4; ++i) {
        int idx = i * 256 + t;
        int r = idx >> 5, col = idx & 31;
        tile[r][col] = tokens[((size_t)(n * 1024 + c0 + r)) * 1024 + l0 + col];
    }
    __syncthreads();
#pragma unroll
    for (int i = 0; i < 4; ++i) {
        int idx = i * 256 + t;
        int r = idx >> 5, col = idx & 31;
        g_tokT[((size_t)(n * 1024 + l0 + r)) * 1024 + c0 + col] = f2tf(tile[col][r]);
    }
}

// ---------------- shared GEMM pieces ----------------
// smem tile: 128 rows x 32 k, row pitch 36 floats (144B)
__device__ __forceinline__ void load_tile(uint32_t smem_dst, const float* src, int row_stride, int t)
{
#pragma unroll
    for (int i = 0; i < 4; ++i) {
        int idx = i * 256 + t;
        int row = idx >> 3, k4 = idx & 7;
        CPA(smem_dst + (uint32_t)(row * 144 + k4 * 16), src + (size_t)row * row_stride + k4 * 4);
    }
}

__device__ __forceinline__ void wgemm_chunk(const float* As, const float* Bs,
                                            float C[4][4][4], int lane, int m0, int n0)
{
    const uint32_t* Au = (const uint32_t*)As;
    const uint32_t* Bu = (const uint32_t*)Bs;
    int ar = m0 + (lane >> 2);
    int ac = lane & 3;
    int bn = n0 + (lane >> 2);
#pragma unroll
    for (int ks = 0; ks < 4; ++ks) {
        uint32_t a[4][4], b[4][2];
        int k = ks * 8 + ac;
#pragma unroll
        for (int mi = 0; mi < 4; ++mi) {
            int r = ar + mi * 16;
            a[mi][0] = Au[r * 36 + k];
            a[mi][1] = Au[(r + 8) * 36 + k];
            a[mi][2] = Au[r * 36 + k + 4];
            a[mi][3] = Au[(r + 8) * 36 + k + 4];
        }
#pragma unroll
        for (int ni = 0; ni < 4; ++ni) {
            int c = bn + ni * 8;
            b[ni][0] = Bu[c * 36 + k];
            b[ni][1] = Bu[c * 36 + k + 4];
        }
#pragma unroll
        for (int mi = 0; mi < 4; ++mi)
#pragma unroll
            for (int ni = 0; ni < 4; ++ni)
                mma8(C[mi][ni], a[mi], b[ni]);
    }
}

#define GSTAGE 18432u  // bytes per operand tile
#define GEMM_SMEM 73728

// ---------------- qkv conv GEMM ----------------
__global__ __launch_bounds__(256, 2) void qkv_tc()
{
    extern __shared__ float sm[];
    uint32_t sb = smem_u32(sm);
    int t = threadIdx.x, wid = t >> 5, lane = t & 31;
    int lt = blockIdx.x, rb = blockIdx.y, ng = blockIdx.z;
    int n = ng >> 3, g = ng & 7;
    int l0 = lt * 128;
    int m0 = (wid & 1) * 64, n0 = (wid >> 1) * 32;
    const float* Ag = g_wg + (size_t)(g * 256 + rb * 128) * 128;
    const float* Bg = g_tokT + ((size_t)(n * 1024 + l0)) * 1024 + g * 128;

    float C[4][4][4] = {};
    load_tile(sb, Ag, 128, t);
    load_tile(sb + GSTAGE, Bg, 1024, t);
    CPC();
    for (int c = 0; c < 4; ++c) {
        CPW0();
        __syncthreads();
        if (c + 1 < 4) {
            uint32_t so = (uint32_t)(((c + 1) & 1) * 2) * GSTAGE;
            load_tile(sb + so, Ag + (c + 1) * 32, 128, t);
            load_tile(sb + so + GSTAGE, Bg + (c + 1) * 32, 1024, t);
            CPC();
        }
        const float* As = sm + (c & 1) * 9216;
        wgemm_chunk(As, As + 4608, C, lane, m0, n0);
    }
    __syncthreads();

    float* Sb = sm;  // [128][33]
    for (int ch = 0; ch < 4; ++ch) {
        if ((wid >> 1) == ch) {
#pragma unroll
            for (int mi = 0; mi < 4; ++mi)
#pragma unroll
                for (int ni = 0; ni < 4; ++ni) {
                    int m = m0 + mi * 16 + (lane >> 2);
                    int q = ni * 8 + 2 * (lane & 3);
                    Sb[m * 33 + q] = C[mi][ni][0];
                    Sb[m * 33 + q + 1] = C[mi][ni][1];
                    Sb[(m + 8) * 33 + q] = C[mi][ni][2];
                    Sb[(m + 8) * 33 + q + 1] = C[mi][ni][3];
                }
        }
        __syncthreads();
        if (rb == 0) {
#pragma unroll
            for (int i = 0; i < 8; ++i) {
                int m = t & 63, l = (t >> 6) + 4 * i;
                int h = 2 * g + (m >> 5), d = m & 31;
                size_t base = (((size_t)(n * 16 + h)) * 1024 + l0 + ch * 32 + l) * 32 + d;
                g_kbuf[base] = f2tf(Sb[m * 33 + l] + g_bg[g * 256 + m]);
                g_qbuf[base] = f2tf(Sb[(m + 64) * 33 + l] + g_bg[g * 256 + 64 + m]);
            }
        } else {
#pragma unroll
            for (int i = 0; i < 16; ++i) {
                int l = t & 31, m = (t >> 5) + 8 * i;
                g_vbuf[((size_t)(n * 1024 + g * 128 + m)) * 1024 + l0 + ch * 32 + l] =
                    f2tf(Sb[m * 33 + l] + g_bg[g * 256 + 128 + m]);
            }
        }
        __syncthreads();
    }
}

// ---------------- ff conv GEMM + residual ----------------
__global__ __launch_bounds__(256, 2) void fconv_tc(float* __restrict__ out)
{
    extern __shared__ float sm[];
    uint32_t sb = smem_u32(sm);
    int t = threadIdx.x, wid = t >> 5, lane = t & 31;
    int lt = blockIdx.x, cb = blockIdx.y, n = blockIdx.z;
    int l0 = lt * 128;
    int m0 = (wid & 1) * 64, n0 = (wid >> 1) * 32;
    const float* Ag = g_wf + (size_t)(cb * 128) * 1024;
    const float* Bg = g_t2T + ((size_t)(n * 1024 + l0)) * 1024;

    float C[4][4][4] = {};
    load_tile(sb, Ag, 1024, t);
    load_tile(sb + GSTAGE, Bg, 1024, t);
    CPC();
    for (int c = 0; c < 32; ++c) {
        CPW0();
        __syncthreads();
        if (c + 1 < 32) {
            uint32_t so = (uint32_t)(((c + 1) & 1) * 2) * GSTAGE;
            load_tile(sb + so, Ag + (c + 1) * 32, 1024, t);
            load_tile(sb + so + GSTAGE, Bg + (c + 1) * 32, 1024, t);
            CPC();
        }
        const float* As = sm + (c & 1) * 9216;
        wgemm_chunk(As, As + 4608, C, lane, m0, n0);
    }
    __syncthreads();

    float* Sb = sm;
    for (int ch = 0; ch < 4; ++ch) {
        if ((wid >> 1) == ch) {
#pragma unroll
            for (int mi = 0; mi < 4; ++mi)
#pragma unroll
                for (int ni = 0; ni < 4; ++ni) {
                    int m = m0 + mi * 16 + (lane >> 2);
                    int q = ni * 8 + 2 * (lane & 3);
                    Sb[m * 33 + q] = C[mi][ni][0];
                    Sb[m * 33 + q + 1] = C[mi][ni][1];
                    Sb[(m + 8) * 33 + q] = C[mi][ni][2];
                    Sb[(m + 8) * 33 + q + 1] = C[mi][ni][3];
                }
        }
        __syncthreads();
#pragma unroll
        for (int i = 0; i < 16; ++i) {
            int l = t & 31, m = (t >> 5) + 8 * i;
            size_t addr = ((size_t)(n * 1024 + cb * 128 + m)) * 1024 + l0 + ch * 32 + l;
            out[addr] = Sb[m * 33 + l] + g_bf[cb * 128 + m] + g_t2[addr];
        }
        __syncthreads();
    }
}

// ---------------- flash attention with mma.sync ----------------
// smem floats: Qs[128*36]=4608 | Ks 2x4608 | Vs 2x8448 | Pt[128*132]=16896 | m/l/f 3x128
#define ATTN_SMEM (48000 * 4)

__device__ __forceinline__ void attn_load_kv(uint32_t sb, const float* Kg, const float* Vg,
                                             int k0, int s, int t)
{
    uint32_t ks = sb + (4608u + (uint32_t)s * 4608u) * 4u;
    uint32_t vs = sb + (13824u + (uint32_t)s * 8448u) * 4u;
#pragma unroll
    for (int i = 0; i < 4; ++i) {
        int idx = i * 256 + t;
        int row = idx >> 3, k4 = idx & 7;
        CPA(ks + (uint32_t)(row * 144 + k4 * 16), Kg + (size_t)(k0 + row) * 32 + k4 * 4);
    }
#pragma unroll
    for (int i = 0; i < 8; ++i) {
        int idx = i * 256 + t;
        int d = idx >> 5, l4 = idx & 31;
        CPA(vs + (uint32_t)(d * 528 + l4 * 16), Vg + (size_t)d * 1024 + k0 + l4 * 4);
    }
}

__global__ __launch_bounds__(256, 1) void attn_tc(const float* __restrict__ tokens)
{
    extern __shared__ float sm[];
    uint32_t sb = smem_u32(sm);
    float* Pt = sm + 30720;
    float* mbuf = sm + 47616;
    float* lbuf = mbuf + 128;
    float* facb = lbuf + 128;

    int t = threadIdx.x, wid = t >> 5, lane = t & 31;
    int qt = blockIdx.x, h = blockIdx.y, n = blockIdx.z;
    int q0g = qt * 128;
    const float* Kg = g_kbuf + ((size_t)(n * 16 + h)) * 1024 * 32;
    const float* Qg = g_qbuf + ((size_t)(n * 16 + h)) * 1024 * 32;
    const float* Vg = g_vbuf + ((size_t)(n * 1024 + h * 64)) * 1024;

    // prologue: Q + K0/V0 in one group
#pragma unroll
    for (int i = 0; i < 4; ++i) {
        int idx = i * 256 + t;
        int row = idx >> 3, k4 = idx & 7;
        CPA(sb + (uint32_t)(row * 144 + k4 * 16), Qg + (size_t)(q0g + row) * 32 + k4 * 4);
    }
    attn_load_kv(sb, Kg, Vg, 0, 0, t);
    CPC();
    if (t < 128) { mbuf[t] = -1e30f; lbuf[t] = 0.f; }

    float CO[2][4][4] = {};
    int m0s = (wid & 1) * 64, n0 = (wid >> 1) * 32, m0o = (wid & 1) * 32;
    int ac = lane & 3;

    for (int kt = 0; kt < 8; ++kt) {
        CPW0();
        __syncthreads();
        if (kt + 1 < 8) { attn_load_kv(sb, Kg, Vg, (kt + 1) * 128, (kt + 1) & 1, t); CPC(); }
        const float* Ks = sm + 4608 + (kt & 1) * 4608;
        const float* Vs = sm + 13824 + (kt & 1) * 8448;

        // ---- S = K . Q^T ----
        float CS[4][4][4] = {};
        {
            const uint32_t* Au = (const uint32_t*)Ks;
            const uint32_t* Bu = (const uint32_t*)sm;  // Qs
            int ar = m0s + (lane >> 2), bn = n0 + (lane >> 2);
#pragma unroll
            for (int ks = 0; ks < 4; ++ks) {
                uint32_t a[4][4], b[4][2];
                int k = ks * 8 + ac;
#pragma unroll
                for (int mi = 0; mi < 4; ++mi) {
                    int r = ar + mi * 16;
                    a[mi][0] = Au[r * 36 + k];
                    a[mi][1] = Au[(r + 8) * 36 + k];
                    a[mi][2] = Au[r * 36 + k + 4];
                    a[mi][3] = Au[(r + 8) * 36 + k + 4];
                }
#pragma unroll
                for (int ni = 0; ni < 4; ++ni) {
                    int c = bn + ni * 8;
                    b[ni][0] = Bu[c * 36 + k];
                    b[ni][1] = Bu[c * 36 + k + 4];
                }
#pragma unroll
                for (int mi = 0; mi < 4; ++mi)
#pragma unroll
                    for (int ni = 0; ni < 4; ++ni)
                        mma8(CS[mi][ni], a[mi], b[ni]);
            }
        }
        // ---- stage S -> Pt[q][k] (transposed) ----
#pragma unroll
        for (int mi = 0; mi < 4; ++mi)
#pragma unroll
            for (int ni = 0; ni < 4; ++ni) {
                int kk = m0s + mi * 16 + (lane >> 2);
                int q = n0 + ni * 8 + 2 * (lane & 3);
                Pt[q * 132 + kk] = CS[mi][ni][0];
                Pt[(q + 1) * 132 + kk] = CS[mi][ni][1];
                Pt[q * 132 + kk + 8] = CS[mi][ni][2];
                Pt[(q + 1) * 132 + kk + 8] = CS[mi][ni][3];
            }
        __syncthreads();
        // ---- online softmax: warp per row, 16 rows/warp ----
#pragma unroll 2
        for (int rr = 0; rr < 16; ++rr) {
            int q = wid * 16 + rr;
            float4 p = *(float4*)&Pt[q * 132 + lane * 4];
            float lm = fmaxf(fmaxf(p.x, p.y), fmaxf(p.z, p.w));
#pragma unroll
            for (int o = 16; o; o >>= 1) lm = fmaxf(lm, __shfl_xor_sync(0xffffffffu, lm, o));
            float mo = mbuf[q];
            float mn = fmaxf(mo, lm);
            float4 e;
            e.x = __expf(p.x - mn); e.y = __expf(p.y - mn);
            e.z = __expf(p.z - mn); e.w = __expf(p.w - mn);
            float s = e.x + e.y + e.z + e.w;
#pragma unroll
            for (int o = 16; o; o >>= 1) s += __shfl_xor_sync(0xffffffffu, s, o);
            e.x = f2tf(e.x); e.y = f2tf(e.y); e.z = f2tf(e.z); e.w = f2tf(e.w);
            *(float4*)&Pt[q * 132 + lane * 4] = e;
            if (lane == 0) {
                float f = __expf(mo - mn);
                mbuf[q] = mn; facb[q] = f;
                lbuf[q] = lbuf[q] * f + s;
            }
        }
        __syncthreads();
        // ---- rescale O, then O += V . P ----
        float fq[4][2];
#pragma unroll
        for (int ni = 0; ni < 4; ++ni) {
            int q = n0 + ni * 8 + 2 * (lane & 3);
            fq[ni][0] = facb[q]; fq[ni][1] = facb[q + 1];
        }
#pragma unroll
        for (int mi = 0; mi < 2; ++mi)
#pragma unroll
            for (int ni = 0; ni < 4; ++ni) {
                CO[mi][ni][0] *= fq[ni][0]; CO[mi][ni][1] *= fq[ni][1];
                CO[mi][ni][2] *= fq[ni][0]; CO[mi][ni][3] *= fq[ni][1];
            }
        {
            const uint32_t* Au = (const uint32_t*)Vs;
            const uint32_t* Bu = (const uint32_t*)Pt;
            int ar = m0o + (lane >> 2), bn = n0 + (lane >> 2);
#pragma unroll
            for (int ks = 0; ks < 16; ++ks) {
                uint32_t a[2][4], b[4][2];
                int k = ks * 8 + ac;
#pragma unroll
                for (int mi = 0; mi < 2; ++mi) {
                    int r = ar + mi * 16;
                    a[mi][0] = Au[r * 132 + k];
                    a[mi][1] = Au[(r + 8) * 132 + k];
                    a[mi][2] = Au[r * 132 + k + 4];
                    a[mi][3] = Au[(r + 8) * 132 + k + 4];
                }
#pragma unroll
                for (int ni = 0; ni < 4; ++ni) {
                    int c = bn + ni * 8;
                    b[ni][0] = Bu[c * 132 + k];
                    b[ni][1] = Bu[c * 132 + k + 4];
                }
#pragma unroll
                for (int mi = 0; mi < 2; ++mi)
#pragma unroll
                    for (int ni = 0; ni < 4; ++ni)
                        mma8(CO[mi][ni], a[mi], b[ni]);
            }
        }
    }
    // ---- epilogue ----
    __syncthreads();
    float* Ob = sm + 4608;  // [64][133]
    float lq[4][2];
#pragma unroll
    for (int ni = 0; ni < 4; ++ni) {
        int q = n0 + ni * 8 + 2 * (lane & 3);
        lq[ni][0] = 1.0f / lbuf[q]; lq[ni][1] = 1.0f / lbuf[q + 1];
    }
#pragma unroll
    for (int mi = 0; mi < 2; ++mi)
#pragma unroll
        for (int ni = 0; ni < 4; ++ni) {
            int d = m0o + mi * 16 + (lane >> 2);
            int q = n0 + ni * 8 + 2 * (lane & 3);
            Ob[d * 133 + q] = CO[mi][ni][0] * lq[ni][0];
            Ob[d * 133 + q + 1] = CO[mi][ni][1] * lq[ni][1];
            Ob[(d + 8) * 133 + q] = CO[mi][ni][2] * lq[ni][0];
            Ob[(d + 8) * 133 + q + 1] = CO[mi][ni][3] * lq[ni][1];
        }
    __syncthreads();
#pragma unroll
    for (int i = 0; i < 32; ++i) {
        int l = t & 127, d = (t >> 7) + 2 * i;
        size_t addr = ((size_t)(n * 1024 + h * 64 + d)) * 1024 + q0g + l;
        float r = tokens[addr] + Ob[d * 133 + l];
        g_t2[addr] = r;
        Ob[d * 133 + l] = r;
    }
    __syncthreads();
#pragma unroll
    for (int i = 0; i < 32; ++i) {
        int d = t & 63, l = (t >> 6) + 4 * i;
        g_t2T[((size_t)(n * 1024 + q0g + l)) * 1024 + h * 64 + d] = f2tf(Ob[d * 133 + l]);
    }
}

// ---------------- launch ----------------
extern "C" void kernel_launch(void* const* d_in, const int* in_sizes, int n_in,
                              void* d_out, int out_size)
{
    (void)in_sizes; (void)n_in; (void)out_size;
    const float* tokens = (const float*)d_in[0];
    const float* p[24];
    for (int i = 0; i < 24; ++i) p[i] = (const float*)d_in[1 + i];

    cudaFuncSetAttribute(qkv_tc, cudaFuncAttributeMaxDynamicSharedMemorySize, GEMM_SMEM);
    cudaFuncSetAttribute(fconv_tc, cudaFuncAttributeMaxDynamicSharedMemorySize, GEMM_SMEM);
    cudaFuncSetAttribute(attn_tc, cudaFuncAttributeMaxDynamicSharedMemorySize, ATTN_SMEM);

    int total_prep = 1024 * 1024 + 8 * 256 * 128 + 8 * 256 + 1024;
    prep_kernel<<<(total_prep + 255) / 256, 256>>>(
        p[0], p[1], p[2], p[3], p[4], p[5],
        p[6], p[7], p[8], p[9], p[10], p[11],
        p[12], p[13], p[14], p[15], p[16], p[17],
        p[18], p[19], p[20], p[21], p[22], p[23]);

    transpose_kernel<<<dim3(32, 32, 8), 256>>>(tokens);
    qkv_tc<<<dim3(8, 2, 64), 256, GEMM_SMEM>>>();
    attn_tc<<<dim3(8, 16, 8), 256, ATTN_SMEM>>>(tokens);
    fconv_tc<<<dim3(8, 8, 8), 256, GEMM_SMEM>>>((float*)d_out);
}

// round 4
// speedup vs baseline: 2.4749x; 1.3612x over previous
#include <cuda_runtime.h>
#include <cstdint>
#include <math.h>

// ---------------- scratch ----------------
__device__ float g_kbuf[8 * 16 * 1024 * 32];   // [n][h][l][32d] tf32
__device__ float g_qbuf[8 * 16 * 1024 * 32];   // [n][h][l][32d] tf32 (pre-scaled 1/32)
__device__ float g_vbuf[8 * 1024 * 1024];      // [n][c][l] tf32
__device__ float g_t2 [8 * 1024 * 1024];       // [n][c][l] fp32 (attn + residual)
__device__ float g_t2T[8 * 1024 * 1024];       // [n][l][c] tf32
__device__ float g_tokT[8 * 1024 * 1024];      // [n][l][c] tf32
__device__ float g_wg[8 * 256 * 128];          // [g][r][k] tf32
__device__ float g_bg[8 * 256];
__device__ float g_wf[1024 * 1024];            // [c][k] tf32
__device__ float g_bf[1024];

// ---------------- helpers ----------------
__device__ __forceinline__ uint32_t smem_u32(const void* p) {
    uint32_t a;
    asm("{ .reg .u64 t; cvta.to.shared.u64 t, %1; cvt.u32.u64 %0, t; }" : "=r"(a) : "l"(p));
    return a;
}
__device__ __forceinline__ float f2tf(float x) {
    uint32_t r;
    asm("cvt.rna.tf32.f32 %0, %1;" : "=r"(r) : "f"(x));
    return __uint_as_float(r);
}
#define CPA(dst, src) asm volatile("cp.async.cg.shared.global [%0], [%1], 16;" :: "r"(dst), "l"(__cvta_generic_to_global(src)))
#define CPC()  asm volatile("cp.async.commit_group;" ::: "memory")
#define CPW0() asm volatile("cp.async.wait_group 0;" ::: "memory")

__device__ __forceinline__ void mma8(float* d, const uint32_t* a, const uint32_t* b) {
    asm volatile(
        "mma.sync.aligned.m16n8k8.row.col.f32.tf32.tf32.f32 "
        "{%0,%1,%2,%3}, {%4,%5,%6,%7}, {%8,%9}, {%0,%1,%2,%3};"
        : "+f"(d[0]), "+f"(d[1]), "+f"(d[2]), "+f"(d[3])
        : "r"(a[0]), "r"(a[1]), "r"(a[2]), "r"(a[3]), "r"(b[0]), "r"(b[1]));
}

// ---------------- prep ----------------
__global__ void prep_kernel(
    const float* __restrict__ kw, const float* __restrict__ kb, const float* __restrict__ kga,
    const float* __restrict__ kbe, const float* __restrict__ km, const float* __restrict__ kv,
    const float* __restrict__ qw, const float* __restrict__ qb, const float* __restrict__ qga,
    const float* __restrict__ qbe, const float* __restrict__ qm, const float* __restrict__ qv,
    const float* __restrict__ vw, const float* __restrict__ vb, const float* __restrict__ vga,
    const float* __restrict__ vbe, const float* __restrict__ vm, const float* __restrict__ vv,
    const float* __restrict__ fw, const float* __restrict__ fb, const float* __restrict__ fga,
    const float* __restrict__ fbe, const float* __restrict__ fm, const float* __restrict__ fv)
{
    int id = blockIdx.x * blockDim.x + threadIdx.x;
    if (id < 1024 * 1024) {
        int c = id >> 10;
        float inv = fga[c] * rsqrtf(fv[c] + 1e-5f);
        g_wf[id] = f2tf(fw[id] * inv);
        return;
    }
    int id2 = id - 1024 * 1024;
    if (id2 < 8 * 256 * 128) {
        int k = id2 & 127;
        int r = (id2 >> 7) & 255;
        int g = id2 >> 15;
        float w;
        if (r < 64) {
            int c = g * 64 + r;
            float inv = kga[c] * rsqrtf(kv[c] + 1e-5f);
            w = kw[c * 128 + k] * inv;
        } else if (r < 128) {
            int c = g * 64 + (r - 64);
            float inv = qga[c] * rsqrtf(qv[c] + 1e-5f);
            w = qw[c * 128 + k] * inv * 0.03125f;
        } else {
            int c = g * 128 + (r - 128);
            float inv = vga[c] * rsqrtf(vv[c] + 1e-5f);
            w = vw[c * 128 + k] * inv;
        }
        g_wg[id2] = f2tf(w);
        return;
    }
    int id3 = id2 - 8 * 256 * 128;
    if (id3 < 8 * 256) {
        int g = id3 >> 8, r = id3 & 255;
        float bias;
        if (r < 64) {
            int c = g * 64 + r;
            float inv = kga[c] * rsqrtf(kv[c] + 1e-5f);
            bias = kb[c] * inv + kbe[c] - km[c] * inv;
        } else if (r < 128) {
            int c = g * 64 + (r - 64);
            float inv = qga[c] * rsqrtf(qv[c] + 1e-5f);
            bias = (qb[c] * inv + qbe[c] - qm[c] * inv) * 0.03125f;
        } else {
            int c = g * 128 + (r - 128);
            float inv = vga[c] * rsqrtf(vv[c] + 1e-5f);
            bias = vb[c] * inv + vbe[c] - vm[c] * inv;
        }
        g_bg[id3] = bias;
        return;
    }
    int c = id3 - 8 * 256;
    if (c < 1024) {
        float inv = fga[c] * rsqrtf(fv[c] + 1e-5f);
        g_bf[c] = fb[c] * inv + fbe[c] - fm[c] * inv;
    }
}

// ---------------- tokens transpose ----------------
__global__ __launch_bounds__(256) void transpose_kernel(const float* __restrict__ tokens)
{
    __shared__ float tile[32][33];
    int l0 = blockIdx.x * 32, c0 = blockIdx.y * 32, n = blockIdx.z;
    int t = threadIdx.x;
#pragma unroll
    for (int i = 0; i < 4; ++i) {
        int idx = i * 256 + t;
        int r = idx >> 5, col = idx & 31;
        tile[r][col] = tokens[((size_t)(n * 1024 + c0 + r)) * 1024 + l0 + col];
    }
    __syncthreads();
#pragma unroll
    for (int i = 0; i < 4; ++i) {
        int idx = i * 256 + t;
        int r = idx >> 5, col = idx & 31;
        g_tokT[((size_t)(n * 1024 + l0 + r)) * 1024 + c0 + col] = f2tf(tile[col][r]);
    }
}

// ---------------- shared GEMM pieces ----------------
__device__ __forceinline__ void load_tile(uint32_t smem_dst, const float* src, int row_stride, int t)
{
#pragma unroll
    for (int i = 0; i < 4; ++i) {
        int idx = i * 256 + t;
        int row = idx >> 3, k4 = idx & 7;
        CPA(smem_dst + (uint32_t)(row * 144 + k4 * 16), src + (size_t)row * row_stride + k4 * 4);
    }
}

__device__ __forceinline__ void wgemm_chunk(const float* As, const float* Bs,
                                            float C[4][4][4], int lane, int m0, int n0)
{
    const uint32_t* Au = (const uint32_t*)As;
    const uint32_t* Bu = (const uint32_t*)Bs;
    int ar = m0 + (lane >> 2);
    int ac = lane & 3;
    int bn = n0 + (lane >> 2);
#pragma unroll
    for (int ks = 0; ks < 4; ++ks) {
        uint32_t a[4][4], b[4][2];
        int k = ks * 8 + ac;
#pragma unroll
        for (int mi = 0; mi < 4; ++mi) {
            int r = ar + mi * 16;
            a[mi][0] = Au[r * 36 + k];
            a[mi][1] = Au[(r + 8) * 36 + k];
            a[mi][2] = Au[r * 36 + k + 4];
            a[mi][3] = Au[(r + 8) * 36 + k + 4];
        }
#pragma unroll
        for (int ni = 0; ni < 4; ++ni) {
            int c = bn + ni * 8;
            b[ni][0] = Bu[c * 36 + k];
            b[ni][1] = Bu[c * 36 + k + 4];
        }
#pragma unroll
        for (int mi = 0; mi < 4; ++mi)
#pragma unroll
            for (int ni = 0; ni < 4; ++ni)
                mma8(C[mi][ni], a[mi], b[ni]);
    }
}

#define GSTAGE 18432u
#define GEMM_SMEM 73728

// ---------------- qkv conv GEMM ----------------
__global__ __launch_bounds__(256, 2) void qkv_tc()
{
    extern __shared__ float sm[];
    uint32_t sb = smem_u32(sm);
    int t = threadIdx.x, wid = t >> 5, lane = t & 31;
    int lt = blockIdx.x, rb = blockIdx.y, ng = blockIdx.z;
    int n = ng >> 3, g = ng & 7;
    int l0 = lt * 128;
    int m0 = (wid & 1) * 64, n0 = (wid >> 1) * 32;
    const float* Ag = g_wg + (size_t)(g * 256 + rb * 128) * 128;
    const float* Bg = g_tokT + ((size_t)(n * 1024 + l0)) * 1024 + g * 128;

    float C[4][4][4] = {};
    load_tile(sb, Ag, 128, t);
    load_tile(sb + GSTAGE, Bg, 1024, t);
    CPC();
    for (int c = 0; c < 4; ++c) {
        CPW0();
        __syncthreads();
        if (c + 1 < 4) {
            uint32_t so = (uint32_t)(((c + 1) & 1) * 2) * GSTAGE;
            load_tile(sb + so, Ag + (c + 1) * 32, 128, t);
            load_tile(sb + so + GSTAGE, Bg + (c + 1) * 32, 1024, t);
            CPC();
        }
        const float* As = sm + (c & 1) * 9216;
        wgemm_chunk(As, As + 4608, C, lane, m0, n0);
    }
    __syncthreads();

    float* Sb = sm;
    for (int ch = 0; ch < 4; ++ch) {
        if ((wid >> 1) == ch) {
#pragma unroll
            for (int mi = 0; mi < 4; ++mi)
#pragma unroll
                for (int ni = 0; ni < 4; ++ni) {
                    int m = m0 + mi * 16 + (lane >> 2);
                    int q = ni * 8 + 2 * (lane & 3);
                    Sb[m * 33 + q] = C[mi][ni][0];
                    Sb[m * 33 + q + 1] = C[mi][ni][1];
                    Sb[(m + 8) * 33 + q] = C[mi][ni][2];
                    Sb[(m + 8) * 33 + q + 1] = C[mi][ni][3];
                }
        }
        __syncthreads();
        if (rb == 0) {
#pragma unroll
            for (int i = 0; i < 8; ++i) {
                int m = t & 63, l = (t >> 6) + 4 * i;
                int h = 2 * g + (m >> 5), d = m & 31;
                size_t base = (((size_t)(n * 16 + h)) * 1024 + l0 + ch * 32 + l) * 32 + d;
                g_kbuf[base] = f2tf(Sb[m * 33 + l] + g_bg[g * 256 + m]);
                g_qbuf[base] = f2tf(Sb[(m + 64) * 33 + l] + g_bg[g * 256 + 64 + m]);
            }
        } else {
#pragma unroll
            for (int i = 0; i < 16; ++i) {
                int l = t & 31, m = (t >> 5) + 8 * i;
                g_vbuf[((size_t)(n * 1024 + g * 128 + m)) * 1024 + l0 + ch * 32 + l] =
                    f2tf(Sb[m * 33 + l] + g_bg[g * 256 + 128 + m]);
            }
        }
        __syncthreads();
    }
}

// ---------------- ff conv GEMM + residual ----------------
__global__ __launch_bounds__(256, 2) void fconv_tc(float* __restrict__ out)
{
    extern __shared__ float sm[];
    uint32_t sb = smem_u32(sm);
    int t = threadIdx.x, wid = t >> 5, lane = t & 31;
    int lt = blockIdx.x, cb = blockIdx.y, n = blockIdx.z;
    int l0 = lt * 128;
    int m0 = (wid & 1) * 64, n0 = (wid >> 1) * 32;
    const float* Ag = g_wf + (size_t)(cb * 128) * 1024;
    const float* Bg = g_t2T + ((size_t)(n * 1024 + l0)) * 1024;

    float C[4][4][4] = {};
    load_tile(sb, Ag, 1024, t);
    load_tile(sb + GSTAGE, Bg, 1024, t);
    CPC();
    for (int c = 0; c < 32; ++c) {
        CPW0();
        __syncthreads();
        if (c + 1 < 32) {
            uint32_t so = (uint32_t)(((c + 1) & 1) * 2) * GSTAGE;
            load_tile(sb + so, Ag + (c + 1) * 32, 1024, t);
            load_tile(sb + so + GSTAGE, Bg + (c + 1) * 32, 1024, t);
            CPC();
        }
        const float* As = sm + (c & 1) * 9216;
        wgemm_chunk(As, As + 4608, C, lane, m0, n0);
    }
    __syncthreads();

    float* Sb = sm;
    for (int ch = 0; ch < 4; ++ch) {
        if ((wid >> 1) == ch) {
#pragma unroll
            for (int mi = 0; mi < 4; ++mi)
#pragma unroll
                for (int ni = 0; ni < 4; ++ni) {
                    int m = m0 + mi * 16 + (lane >> 2);
                    int q = ni * 8 + 2 * (lane & 3);
                    Sb[m * 33 + q] = C[mi][ni][0];
                    Sb[m * 33 + q + 1] = C[mi][ni][1];
                    Sb[(m + 8) * 33 + q] = C[mi][ni][2];
                    Sb[(m + 8) * 33 + q + 1] = C[mi][ni][3];
                }
        }
        __syncthreads();
#pragma unroll
        for (int i = 0; i < 16; ++i) {
            int l = t & 31, m = (t >> 5) + 8 * i;
            size_t addr = ((size_t)(n * 1024 + cb * 128 + m)) * 1024 + l0 + ch * 32 + l;
            out[addr] = Sb[m * 33 + l] + g_bf[cb * 128 + m] + g_t2[addr];
        }
        __syncthreads();
    }
}

// ---------------- flash attention: register-resident softmax ----------------
// smem floats: Ks 2x(64x36)=4608 | Vs 2x(64x68)=8704  => 13312 floats = 52KB
// epilogue reuses: Ob[64][133] = 8512 floats
#define ATTN_SMEM (13312 * 4)
#define KSP 36
#define VSP 68

__global__ __launch_bounds__(256, 2) void attn_tc(const float* __restrict__ tokens)
{
    extern __shared__ float sm[];
    uint32_t sb = smem_u32(sm);
    float* Ks[2] = { sm, sm + 2304 };
    float* Vs[2] = { sm + 4608, sm + 8960 };
    uint32_t ksb[2] = { sb, sb + 2304 * 4 };
    uint32_t vsb[2] = { sb + 4608 * 4, sb + 8960 * 4 };

    int t = threadIdx.x, wid = t >> 5, lane = t & 31;
    int r4 = lane >> 2, j = lane & 3;
    int qt = blockIdx.x, h = blockIdx.y, n = blockIdx.z;
    int q0g = qt * 128, q0w = wid * 16;
    const float* Kg = g_kbuf + ((size_t)(n * 16 + h)) * 1024 * 32;
    const float* Qg = g_qbuf + ((size_t)(n * 16 + h)) * 1024 * 32;
    const float* Vg = g_vbuf + ((size_t)(n * 1024 + h * 64)) * 1024;

    // Q fragments (held all kernel): 16q x 32d per warp
    uint32_t aq[4][4];
#pragma unroll
    for (int ds = 0; ds < 4; ++ds) {
        const float* qb = Qg + (size_t)(q0g + q0w + r4) * 32 + ds * 8 + j;
        aq[ds][0] = __float_as_uint(qb[0]);
        aq[ds][1] = __float_as_uint(qb[8 * 32]);
        aq[ds][2] = __float_as_uint(qb[4]);
        aq[ds][3] = __float_as_uint(qb[8 * 32 + 4]);
    }

    // prologue loads: tile 0
#pragma unroll
    for (int i = 0; i < 2; ++i) {
        int idx = i * 256 + t;
        int row = idx >> 3, d4 = idx & 7;
        CPA(ksb[0] + (uint32_t)(row * KSP + d4 * 4) * 4, Kg + (size_t)row * 32 + d4 * 4);
    }
#pragma unroll
    for (int i = 0; i < 4; ++i) {
        int idx = i * 256 + t;
        int row = idx >> 4, k4 = idx & 15;
        CPA(vsb[0] + (uint32_t)(row * VSP + k4 * 4) * 4, Vg + (size_t)row * 1024 + k4 * 4);
    }
    CPC();

    float CO[8][4] = {};
    float mo0 = -1e30f, mo1 = -1e30f, l0 = 0.f, l1 = 0.f;
    int src1 = (lane & ~3) | (j >> 1);
    int src2 = src1 + 2;
    bool odd = j & 1;

    for (int kt = 0; kt < 16; ++kt) {
        int buf = kt & 1;
        CPW0();
        __syncthreads();
        if (kt + 1 < 16) {
            int nb = (kt + 1) & 1;
            int k0 = (kt + 1) * 64;
#pragma unroll
            for (int i = 0; i < 2; ++i) {
                int idx = i * 256 + t;
                int row = idx >> 3, d4 = idx & 7;
                CPA(ksb[nb] + (uint32_t)(row * KSP + d4 * 4) * 4, Kg + (size_t)(k0 + row) * 32 + d4 * 4);
            }
#pragma unroll
            for (int i = 0; i < 4; ++i) {
                int idx = i * 256 + t;
                int row = idx >> 4, k4 = idx & 15;
                CPA(vsb[nb] + (uint32_t)(row * VSP + k4 * 4) * 4, Vg + (size_t)row * 1024 + k0 + k4 * 4);
            }
            CPC();
        }
        const uint32_t* Ksu = (const uint32_t*)Ks[buf];
        const uint32_t* Vsu = (const uint32_t*)Vs[buf];

        // ---- S = Q . K^T : 16q x 64k ----
        float CS[8][4] = {};
#pragma unroll
        for (int ds = 0; ds < 4; ++ds) {
            int kk = ds * 8 + j;
#pragma unroll
            for (int nt = 0; nt < 8; ++nt) {
                uint32_t b[2];
                b[0] = Ksu[(nt * 8 + r4) * KSP + kk];
                b[1] = Ksu[(nt * 8 + r4) * KSP + kk + 4];
                mma8(CS[nt], aq[ds], b);
            }
        }
        // ---- online softmax in registers ----
        float mt0 = -1e30f, mt1 = -1e30f;
#pragma unroll
        for (int nt = 0; nt < 8; ++nt) {
            mt0 = fmaxf(mt0, fmaxf(CS[nt][0], CS[nt][1]));
            mt1 = fmaxf(mt1, fmaxf(CS[nt][2], CS[nt][3]));
        }
        mt0 = fmaxf(mt0, __shfl_xor_sync(0xffffffffu, mt0, 1));
        mt0 = fmaxf(mt0, __shfl_xor_sync(0xffffffffu, mt0, 2));
        mt1 = fmaxf(mt1, __shfl_xor_sync(0xffffffffu, mt1, 1));
        mt1 = fmaxf(mt1, __shfl_xor_sync(0xffffffffu, mt1, 2));
        float mn0 = fmaxf(mo0, mt0), mn1 = fmaxf(mo1, mt1);
        float fac0 = __expf(mo0 - mn0), fac1 = __expf(mo1 - mn1);
        float s0 = 0.f, s1 = 0.f;
#pragma unroll
        for (int nt = 0; nt < 8; ++nt) {
            float e0 = __expf(CS[nt][0] - mn0);
            float e1 = __expf(CS[nt][1] - mn0);
            float e2 = __expf(CS[nt][2] - mn1);
            float e3 = __expf(CS[nt][3] - mn1);
            s0 += e0 + e1; s1 += e2 + e3;
            CS[nt][0] = f2tf(e0); CS[nt][1] = f2tf(e1);
            CS[nt][2] = f2tf(e2); CS[nt][3] = f2tf(e3);
        }
        s0 += __shfl_xor_sync(0xffffffffu, s0, 1);
        s0 += __shfl_xor_sync(0xffffffffu, s0, 2);
        s1 += __shfl_xor_sync(0xffffffffu, s1, 1);
        s1 += __shfl_xor_sync(0xffffffffu, s1, 2);
        l0 = l0 * fac0 + s0; l1 = l1 * fac1 + s1;
        mo0 = mn0; mo1 = mn1;
        // rescale O
#pragma unroll
        for (int dt = 0; dt < 8; ++dt) {
            CO[dt][0] *= fac0; CO[dt][1] *= fac0;
            CO[dt][2] *= fac1; CO[dt][3] *= fac1;
        }
        // ---- O += P . V^T : permute P(C-layout) -> A-layout per 8-k tile ----
#pragma unroll
        for (int kt2 = 0; kt2 < 8; ++kt2) {
            float v0 = __shfl_sync(0xffffffffu, CS[kt2][0], src1);
            float v1 = __shfl_sync(0xffffffffu, CS[kt2][1], src1);
            float w0 = __shfl_sync(0xffffffffu, CS[kt2][2], src1);
            float w1 = __shfl_sync(0xffffffffu, CS[kt2][3], src1);
            float x0 = __shfl_sync(0xffffffffu, CS[kt2][0], src2);
            float x1 = __shfl_sync(0xffffffffu, CS[kt2][1], src2);
            float y0 = __shfl_sync(0xffffffffu, CS[kt2][2], src2);
            float y1 = __shfl_sync(0xffffffffu, CS[kt2][3], src2);
            uint32_t ap[4];
            ap[0] = __float_as_uint(odd ? v1 : v0);
            ap[1] = __float_as_uint(odd ? w1 : w0);
            ap[2] = __float_as_uint(odd ? x1 : x0);
            ap[3] = __float_as_uint(odd ? y1 : y0);
            int kk = kt2 * 8 + j;
#pragma unroll
            for (int dt = 0; dt < 8; ++dt) {
                uint32_t b[2];
                b[0] = Vsu[(dt * 8 + r4) * VSP + kk];
                b[1] = Vsu[(dt * 8 + r4) * VSP + kk + 4];
                mma8(CO[dt], ap, b);
            }
        }
    }

    // ---- epilogue ----
    __syncthreads();   // done reading K/V buffers; reuse smem as Ob[64][133]
    float* Ob = sm;
    float li0 = 1.0f / l0, li1 = 1.0f / l1;
#pragma unroll
    for (int dt = 0; dt < 8; ++dt) {
        int d = dt * 8 + 2 * j;
        int q = q0w + r4;
        Ob[d * 133 + q] = CO[dt][0] * li0;
        Ob[(d + 1) * 133 + q] = CO[dt][1] * li0;
        Ob[d * 133 + q + 8] = CO[dt][2] * li1;
        Ob[(d + 1) * 133 + q + 8] = CO[dt][3] * li1;
    }
    __syncthreads();
    // residual + write g_t2, store residual back into Ob
#pragma unroll
    for (int i = 0; i < 32; ++i) {
        int q = t & 127, d = (t >> 7) + 2 * i;
        size_t addr = ((size_t)(n * 1024 + h * 64 + d)) * 1024 + q0g + q;
        float r = tokens[addr] + Ob[d * 133 + q];
        g_t2[addr] = r;
        Ob[d * 133 + q] = r;
    }
    __syncthreads();
    // transposed tf32 copy for ff conv
#pragma unroll
    for (int i = 0; i < 32; ++i) {
        int d = t & 63, l = (t >> 6) + 4 * i;
        g_t2T[((size_t)(n * 1024 + q0g + l)) * 1024 + h * 64 + d] = f2tf(Ob[d * 133 + l]);
    }
}

// ---------------- launch ----------------
extern "C" void kernel_launch(void* const* d_in, const int* in_sizes, int n_in,
                              void* d_out, int out_size)
{
    (void)in_sizes; (void)n_in; (void)out_size;
    const float* tokens = (const float*)d_in[0];
    const float* p[24];
    for (int i = 0; i < 24; ++i) p[i] = (const float*)d_in[1 + i];

    cudaFuncSetAttribute(qkv_tc, cudaFuncAttributeMaxDynamicSharedMemorySize, GEMM_SMEM);
    cudaFuncSetAttribute(fconv_tc, cudaFuncAttributeMaxDynamicSharedMemorySize, GEMM_SMEM);
    cudaFuncSetAttribute(attn_tc, cudaFuncAttributeMaxDynamicSharedMemorySize, ATTN_SMEM);

    int total_prep = 1024 * 1024 + 8 * 256 * 128 + 8 * 256 + 1024;
    prep_kernel<<<(total_prep + 255) / 256, 256>>>(
        p[0], p[1], p[2], p[3], p[4], p[5],
        p[6], p[7], p[8], p[9], p[10], p[11],
        p[12], p[13], p[14], p[15], p[16], p[17],
        p[18], p[19], p[20], p[21], p[22], p[23]);

    transpose_kernel<<<dim3(32, 32, 8), 256>>>(tokens);
    qkv_tc<<<dim3(8, 2, 64), 256, GEMM_SMEM>>>();
    attn_tc<<<dim3(8, 16, 8), 256, ATTN_SMEM>>>(tokens);
    fconv_tc<<<dim3(8, 8, 8), 256, GEMM_SMEM>>>((float*)d_out);
}

// round 6
// speedup vs baseline: 4.4132x; 1.7832x over previous
#include <cuda_runtime.h>
#include <cuda_fp16.h>
#include <cstdint>
#include <math.h>

// ---------------- scratch ----------------
__device__ __half g_kbuf[8 * 16 * 1024 * 32];   // [n][h][l][d]
__device__ __half g_qbuf[8 * 16 * 1024 * 32];   // [n][h][l][d] (pre-scaled 1/32)
__device__ __half g_vbuf[8 * 1024 * 1024];      // [n][c][l]
__device__ float  g_t2 [8 * 1024 * 1024];       // [n][c][l] fp32 residual
__device__ __half g_t2T[8 * 1024 * 1024];       // [n][l][c]
__device__ __half g_tokT[8 * 1024 * 1024];      // [n][l][c]
__device__ __half g_wg[8 * 256 * 128];          // [g][r][k]
__device__ float  g_bg[8 * 256];
__device__ __half g_wf[1024 * 1024];            // [c][k]
__device__ float  g_bf[1024];

// ---------------- helpers ----------------
__device__ __forceinline__ uint32_t smem_u32(const void* p) {
    uint32_t a;
    asm("{ .reg .u64 t; cvta.to.shared.u64 t, %1; cvt.u32.u64 %0, t; }" : "=r"(a) : "l"(p));
    return a;
}
#define CPA(dst, src) asm volatile("cp.async.cg.shared.global [%0], [%1], 16;" :: "r"(dst), "l"(__cvta_generic_to_global(src)))
#define CPC()  asm volatile("cp.async.commit_group;" ::: "memory")
#define CPW0() asm volatile("cp.async.wait_group 0;" ::: "memory")
#define LDSM4(r0, r1, r2, r3, a) \
    asm volatile("ldmatrix.sync.aligned.m8n8.x4.shared.b16 {%0,%1,%2,%3}, [%4];" \
        : "=r"(r0), "=r"(r1), "=r"(r2), "=r"(r3) : "r"(a))

__device__ __forceinline__ void mma16(float* d, const uint32_t* a, uint32_t b0, uint32_t b1) {
    asm volatile(
        "mma.sync.aligned.m16n8k16.row.col.f32.f16.f16.f32 "
        "{%0,%1,%2,%3}, {%4,%5,%6,%7}, {%8,%9}, {%0,%1,%2,%3};"
        : "+f"(d[0]), "+f"(d[1]), "+f"(d[2]), "+f"(d[3])
        : "r"(a[0]), "r"(a[1]), "r"(a[2]), "r"(a[3]), "r"(b0), "r"(b1));
}
__device__ __forceinline__ uint32_t packh2(float a, float b) {
    __half2 h = __floats2half2_rn(a, b);
    return *(uint32_t*)&h;
}

// ---------------- prep ----------------
__global__ void prep_kernel(
    const float* __restrict__ kw, const float* __restrict__ kb, const float* __restrict__ kga,
    const float* __restrict__ kbe, const float* __restrict__ km, const float* __restrict__ kv,
    const float* __restrict__ qw, const float* __restrict__ qb, const float* __restrict__ qga,
    const float* __restrict__ qbe, const float* __restrict__ qm, const float* __restrict__ qv,
    const float* __restrict__ vw, const float* __restrict__ vb, const float* __restrict__ vga,
    const float* __restrict__ vbe, const float* __restrict__ vm, const float* __restrict__ vv,
    const float* __restrict__ fw, const float* __restrict__ fb, const float* __restrict__ fga,
    const float* __restrict__ fbe, const float* __restrict__ fm, const float* __restrict__ fv)
{
    int id = blockIdx.x * blockDim.x + threadIdx.x;
    if (id < 1024 * 1024) {
        int c = id >> 10;
        float inv = fga[c] * rsqrtf(fv[c] + 1e-5f);
        g_wf[id] = __float2half(fw[id] * inv);
        return;
    }
    int id2 = id - 1024 * 1024;
    if (id2 < 8 * 256 * 128) {
        int k = id2 & 127;
        int r = (id2 >> 7) & 255;
        int g = id2 >> 15;
        float w;
        if (r < 64) {
            int c = g * 64 + r;
            float inv = kga[c] * rsqrtf(kv[c] + 1e-5f);
            w = kw[c * 128 + k] * inv;
        } else if (r < 128) {
            int c = g * 64 + (r - 64);
            float inv = qga[c] * rsqrtf(qv[c] + 1e-5f);
            w = qw[c * 128 + k] * inv * 0.03125f;
        } else {
            int c = g * 128 + (r - 128);
            float inv = vga[c] * rsqrtf(vv[c] + 1e-5f);
            w = vw[c * 128 + k] * inv;
        }
        g_wg[id2] = __float2half(w);
        return;
    }
    int id3 = id2 - 8 * 256 * 128;
    if (id3 < 8 * 256) {
        int g = id3 >> 8, r = id3 & 255;
        float bias;
        if (r < 64) {
            int c = g * 64 + r;
            float inv = kga[c] * rsqrtf(kv[c] + 1e-5f);
            bias = kb[c] * inv + kbe[c] - km[c] * inv;
        } else if (r < 128) {
            int c = g * 64 + (r - 64);
            float inv = qga[c] * rsqrtf(qv[c] + 1e-5f);
            bias = (qb[c] * inv + qbe[c] - qm[c] * inv) * 0.03125f;
        } else {
            int c = g * 128 + (r - 128);
            float inv = vga[c] * rsqrtf(vv[c] + 1e-5f);
            bias = vb[c] * inv + vbe[c] - vm[c] * inv;
        }
        g_bg[id3] = bias;
        return;
    }
    int c = id3 - 8 * 256;
    if (c < 1024) {
        float inv = fga[c] * rsqrtf(fv[c] + 1e-5f);
        g_bf[c] = fb[c] * inv + fbe[c] - fm[c] * inv;
    }
}

// ---------------- tokens transpose -> half [n][l][c] ----------------
__global__ __launch_bounds__(256) void transpose_kernel(const float* __restrict__ tokens)
{
    __shared__ float tile[32][33];
    int l0 = blockIdx.x * 32, c0 = blockIdx.y * 32, n = blockIdx.z;
    int t = threadIdx.x;
#pragma unroll
    for (int i = 0; i < 4; ++i) {
        int idx = i * 256 + t;
        int r = idx >> 5, col = idx & 31;
        tile[r][col] = tokens[((size_t)(n * 1024 + c0 + r)) * 1024 + l0 + col];
    }
    __syncthreads();
#pragma unroll
    for (int i = 0; i < 4; ++i) {
        int idx = i * 256 + t;
        int r = idx >> 5, col = idx & 31;
        g_tokT[((size_t)(n * 1024 + l0 + r)) * 1024 + c0 + col] = __float2half(tile[col][r]);
    }
}

// ---------------- shared GEMM pieces (fp16, ldmatrix) ----------------
// tile: 128 rows x 32 halves (64B data), row pitch 80B (conflict-free ldmatrix)
#define TP 80u
#define GSTAGE 10240u      // 128 * 80
#define GEMM_SMEM 40960    // 4 stages
__device__ __forceinline__ void load_tile_h(uint32_t dst, const __half* src, int stride_h, int t)
{
#pragma unroll
    for (int i = 0; i < 2; ++i) {
        int idx = i * 256 + t;
        int row = idx >> 2, c16 = idx & 3;
        CPA(dst + (uint32_t)row * TP + (uint32_t)c16 * 16u, src + (size_t)row * stride_h + c16 * 8);
    }
}

__device__ __forceinline__ void wgemm16(uint32_t As, uint32_t Bs, float C[4][4][4], int lane,
                                        int m0, int n0)
{
    int lr = (lane & 7) + ((lane >> 3) & 1) * 8;
    int akb = ((lane >> 4) & 1) * 8;
    int br = (lane & 7) + ((lane >> 4) & 1) * 8;
    int bkb = ((lane >> 3) & 1) * 8;
#pragma unroll
    for (int ks = 0; ks < 2; ++ks) {
        uint32_t a[4][4];
#pragma unroll
        for (int mi = 0; mi < 4; ++mi)
            LDSM4(a[mi][0], a[mi][1], a[mi][2], a[mi][3],
                  As + (uint32_t)(m0 + mi * 16 + lr) * TP + (uint32_t)((ks * 16 + akb) * 2));
#pragma unroll
        for (int np = 0; np < 2; ++np) {
            uint32_t b0, b1, b2, b3;
            LDSM4(b0, b1, b2, b3,
                  Bs + (uint32_t)(n0 + np * 16 + br) * TP + (uint32_t)((ks * 16 + bkb) * 2));
#pragma unroll
            for (int mi = 0; mi < 4; ++mi) {
                mma16(C[mi][np * 2], a[mi], b0, b1);
                mma16(C[mi][np * 2 + 1], a[mi], b2, b3);
            }
        }
    }
}

// ---------------- qkv conv GEMM ----------------
__global__ __launch_bounds__(256, 2) void qkv_tc()
{
    extern __shared__ float sm[];
    uint32_t sb = smem_u32(sm);
    int t = threadIdx.x, wid = t >> 5, lane = t & 31;
    int lt = blockIdx.x, rb = blockIdx.y, ng = blockIdx.z;
    int n = ng >> 3, g = ng & 7;
    int l0 = lt * 128;
    int m0 = (wid & 1) * 64, n0 = (wid >> 1) * 32;
    const __half* Ag = g_wg + (size_t)(g * 256 + rb * 128) * 128;
    const __half* Bg = g_tokT + ((size_t)(n * 1024 + l0)) * 1024 + g * 128;

    float C[4][4][4] = {};
    load_tile_h(sb, Ag, 128, t);
    load_tile_h(sb + 2 * GSTAGE, Bg, 1024, t);
    CPC();
    for (int c = 0; c < 4; ++c) {
        CPW0();
        __syncthreads();
        if (c + 1 < 4) {
            uint32_t so = (uint32_t)((c + 1) & 1) * GSTAGE;
            load_tile_h(sb + so, Ag + (c + 1) * 32, 128, t);
            load_tile_h(sb + so + 2 * GSTAGE, Bg + (c + 1) * 32, 1024, t);
            CPC();
        }
        uint32_t As = sb + (uint32_t)(c & 1) * GSTAGE;
        wgemm16(As, As + 2 * GSTAGE, C, lane, m0, n0);
    }
    __syncthreads();

    float* Sb = sm;  // [128][33]
    int r4 = lane >> 2, j = lane & 3;
    for (int ch = 0; ch < 4; ++ch) {
        if ((wid >> 1) == ch) {
#pragma unroll
            for (int mi = 0; mi < 4; ++mi)
#pragma unroll
                for (int ni = 0; ni < 4; ++ni) {
                    int m = m0 + mi * 16 + r4;
                    int q = ni * 8 + 2 * j;
                    Sb[m * 33 + q] = C[mi][ni][0];
                    Sb[m * 33 + q + 1] = C[mi][ni][1];
                    Sb[(m + 8) * 33 + q] = C[mi][ni][2];
                    Sb[(m + 8) * 33 + q + 1] = C[mi][ni][3];
                }
        }
        __syncthreads();
        if (rb == 0) {
#pragma unroll
            for (int i = 0; i < 8; ++i) {
                int m = t & 63, l = (t >> 6) + 4 * i;
                int h = 2 * g + (m >> 5), d = m & 31;
                size_t base = (((size_t)(n * 16 + h)) * 1024 + l0 + ch * 32 + l) * 32 + d;
                g_kbuf[base] = __float2half(Sb[m * 33 + l] + g_bg[g * 256 + m]);
                g_qbuf[base] = __float2half(Sb[(m + 64) * 33 + l] + g_bg[g * 256 + 64 + m]);
            }
        } else {
#pragma unroll
            for (int i = 0; i < 16; ++i) {
                int l = t & 31, m = (t >> 5) + 8 * i;
                g_vbuf[((size_t)(n * 1024 + g * 128 + m)) * 1024 + l0 + ch * 32 + l] =
                    __float2half(Sb[m * 33 + l] + g_bg[g * 256 + 128 + m]);
            }
        }
        __syncthreads();
    }
}

// ---------------- ff conv GEMM + residual ----------------
__global__ __launch_bounds__(256, 2) void fconv_tc(float* __restrict__ out)
{
    extern __shared__ float sm[];
    uint32_t sb = smem_u32(sm);
    int t = threadIdx.x, wid = t >> 5, lane = t & 31;
    int lt = blockIdx.x, cb = blockIdx.y, n = blockIdx.z;
    int l0 = lt * 128;
    int m0 = (wid & 1) * 64, n0 = (wid >> 1) * 32;
    const __half* Ag = g_wf + (size_t)(cb * 128) * 1024;
    const __half* Bg = g_t2T + ((size_t)(n * 1024 + l0)) * 1024;

    float C[4][4][4] = {};
    load_tile_h(sb, Ag, 1024, t);
    load_tile_h(sb + 2 * GSTAGE, Bg, 1024, t);
    CPC();
    for (int c = 0; c < 32; ++c) {
        CPW0();
        __syncthreads();
        if (c + 1 < 32) {
            uint32_t so = (uint32_t)((c + 1) & 1) * GSTAGE;
            load_tile_h(sb + so, Ag + (c + 1) * 32, 1024, t);
            load_tile_h(sb + so + 2 * GSTAGE, Bg + (c + 1) * 32, 1024, t);
            CPC();
        }
        uint32_t As = sb + (uint32_t)(c & 1) * GSTAGE;
        wgemm16(As, As + 2 * GSTAGE, C, lane, m0, n0);
    }
    __syncthreads();

    float* Sb = sm;
    int r4 = lane >> 2, j = lane & 3;
    for (int ch = 0; ch < 4; ++ch) {
        if ((wid >> 1) == ch) {
#pragma unroll
            for (int mi = 0; mi < 4; ++mi)
#pragma unroll
                for (int ni = 0; ni < 4; ++ni) {
                    int m = m0 + mi * 16 + r4;
                    int q = ni * 8 + 2 * j;
                    Sb[m * 33 + q] = C[mi][ni][0];
                    Sb[m * 33 + q + 1] = C[mi][ni][1];
                    Sb[(m + 8) * 33 + q] = C[mi][ni][2];
                    Sb[(m + 8) * 33 + q + 1] = C[mi][ni][3];
                }
        }
        __syncthreads();
#pragma unroll
        for (int i = 0; i < 16; ++i) {
            int l = t & 31, m = (t >> 5) + 8 * i;
            size_t addr = ((size_t)(n * 1024 + cb * 128 + m)) * 1024 + l0 + ch * 32 + l;
            out[addr] = Sb[m * 33 + l] + g_bf[cb * 128 + m] + g_t2[addr];
        }
        __syncthreads();
    }
}

// ---------------- flash attention (fp16 mma, zero-shuffle P) ----------------
// smem: K 2x(64*80B)=10240 | V 2x(64*144B)=18432 => 28672; epilogue Ob[64][133] f32 = 34048
#define KST 5120u
#define VST 9216u
#define ATTN_SMEM 34048

__global__ __launch_bounds__(256, 2) void attn_tc(const float* __restrict__ tokens)
{
    extern __shared__ float sm[];
    uint32_t sb = smem_u32(sm);

    int t = threadIdx.x, wid = t >> 5, lane = t & 31;
    int r4 = lane >> 2, j = lane & 3;
    int qt = blockIdx.x, h = blockIdx.y, n = blockIdx.z;
    int q0g = qt * 128, q0w = wid * 16;
    const __half* Kg = g_kbuf + ((size_t)(n * 16 + h)) * 1024 * 32;
    const __half* Qg = g_qbuf + ((size_t)(n * 16 + h)) * 1024 * 32;
    const __half* Vg = g_vbuf + ((size_t)(n * 1024 + h * 64)) * 1024;

    // Q fragments (2 k16-chunks), held in regs all kernel
    uint32_t aq[2][4];
#pragma unroll
    for (int ds = 0; ds < 2; ++ds) {
        const __half* qb = Qg + (size_t)(q0g + q0w + r4) * 32 + ds * 16 + 2 * j;
        aq[ds][0] = *(const uint32_t*)qb;
        aq[ds][1] = *(const uint32_t*)(qb + 8 * 32);
        aq[ds][2] = *(const uint32_t*)(qb + 8);
        aq[ds][3] = *(const uint32_t*)(qb + 8 * 32 + 8);
    }

    // prologue: K0/V0
    {
        int row = t >> 2, c16 = t & 3;
        CPA(sb + (uint32_t)row * TP + (uint32_t)c16 * 16u, Kg + (size_t)row * 32 + c16 * 8);
#pragma unroll
        for (int i = 0; i < 2; ++i) {
            int idx = i * 256 + t;
            int vr = idx >> 3, vc = idx & 7;
            CPA(sb + 2u * KST + (uint32_t)(vr * 144 + vc * 16), Vg + (size_t)vr * 1024 + vc * 8);
        }
        CPC();
    }

    float CO[8][4] = {};
    float mo0 = -1e30f, mo1 = -1e30f, l0 = 0.f, l1 = 0.f;
    int lr = (lane & 7) + ((lane >> 4) & 1) * 8;   // B-frag row within 16-group
    int kbo = ((lane >> 3) & 1) * 8;               // B-frag k offset

    for (int kt = 0; kt < 16; ++kt) {
        int buf = kt & 1;
        CPW0();
        __syncthreads();
        if (kt + 1 < 16) {
            int nb = (kt + 1) & 1;
            int k0 = (kt + 1) * 64;
            int row = t >> 2, c16 = t & 3;
            CPA(sb + (uint32_t)nb * KST + (uint32_t)row * TP + (uint32_t)c16 * 16u,
                Kg + (size_t)(k0 + row) * 32 + c16 * 8);
#pragma unroll
            for (int i = 0; i < 2; ++i) {
                int idx = i * 256 + t;
                int vr = idx >> 3, vc = idx & 7;
                CPA(sb + 2u * KST + (uint32_t)nb * VST + (uint32_t)(vr * 144 + vc * 16),
                    Vg + (size_t)vr * 1024 + k0 + vc * 8);
            }
            CPC();
        }
        uint32_t ksm = sb + (uint32_t)buf * KST;
        uint32_t vsm = sb + 2u * KST + (uint32_t)buf * VST;

        // ---- S = Q . K^T : 16q x 64keys ----
        float CS[8][4] = {};
#pragma unroll
        for (int ds = 0; ds < 2; ++ds)
#pragma unroll
            for (int ntp = 0; ntp < 4; ++ntp) {
                uint32_t b0, b1, b2, b3;
                LDSM4(b0, b1, b2, b3,
                      ksm + (uint32_t)(ntp * 16 + lr) * TP + (uint32_t)((ds * 16 + kbo) * 2));
                mma16(CS[2 * ntp], aq[ds], b0, b1);
                mma16(CS[2 * ntp + 1], aq[ds], b2, b3);
            }

        // ---- online softmax in registers ----
        float mt0 = -1e30f, mt1 = -1e30f;
#pragma unroll
        for (int nt = 0; nt < 8; ++nt) {
            mt0 = fmaxf(mt0, fmaxf(CS[nt][0], CS[nt][1]));
            mt1 = fmaxf(mt1, fmaxf(CS[nt][2], CS[nt][3]));
        }
        mt0 = fmaxf(mt0, __shfl_xor_sync(0xffffffffu, mt0, 1));
        mt0 = fmaxf(mt0, __shfl_xor_sync(0xffffffffu, mt0, 2));
        mt1 = fmaxf(mt1, __shfl_xor_sync(0xffffffffu, mt1, 1));
        mt1 = fmaxf(mt1, __shfl_xor_sync(0xffffffffu, mt1, 2));
        float mn0 = fmaxf(mo0, mt0), mn1 = fmaxf(mo1, mt1);
        float fac0 = __expf(mo0 - mn0), fac1 = __expf(mo1 - mn1);
        float s0 = 0.f, s1 = 0.f;
#pragma unroll
        for (int nt = 0; nt < 8; ++nt) {
            float e0 = __expf(CS[nt][0] - mn0);
            float e1 = __expf(CS[nt][1] - mn0);
            float e2 = __expf(CS[nt][2] - mn1);
            float e3 = __expf(CS[nt][3] - mn1);
            s0 += e0 + e1; s1 += e2 + e3;
            CS[nt][0] = e0; CS[nt][1] = e1; CS[nt][2] = e2; CS[nt][3] = e3;
        }
        s0 += __shfl_xor_sync(0xffffffffu, s0, 1);
        s0 += __shfl_xor_sync(0xffffffffu, s0, 2);
        s1 += __shfl_xor_sync(0xffffffffu, s1, 1);
        s1 += __shfl_xor_sync(0xffffffffu, s1, 2);
        l0 = l0 * fac0 + s0; l1 = l1 * fac1 + s1;
        mo0 = mn0; mo1 = mn1;
#pragma unroll
        for (int nt = 0; nt < 8; ++nt) {
            CO[nt][0] *= fac0; CO[nt][1] *= fac0;
            CO[nt][2] *= fac1; CO[nt][3] *= fac1;
        }

        // ---- O += P . V : P A-frags = packed C-layout (zero shuffles) ----
#pragma unroll
        for (int kc = 0; kc < 4; ++kc) {
            uint32_t ap[4];
            ap[0] = packh2(CS[2 * kc][0], CS[2 * kc][1]);
            ap[1] = packh2(CS[2 * kc][2], CS[2 * kc][3]);
            ap[2] = packh2(CS[2 * kc + 1][0], CS[2 * kc + 1][1]);
            ap[3] = packh2(CS[2 * kc + 1][2], CS[2 * kc + 1][3]);
#pragma unroll
            for (int ntp = 0; ntp < 4; ++ntp) {
                uint32_t b0, b1, b2, b3;
                LDSM4(b0, b1, b2, b3,
                      vsm + (uint32_t)((ntp * 16 + lr) * 144 + (kc * 16 + kbo) * 2));
                mma16(CO[2 * ntp], ap, b0, b1);
                mma16(CO[2 * ntp + 1], ap, b2, b3);
            }
        }
    }

    // ---- epilogue ----
    __syncthreads();
    float* Ob = sm;  // [64][133]
    float li0 = 1.0f / l0, li1 = 1.0f / l1;
#pragma unroll
    for (int nt = 0; nt < 8; ++nt) {
        int d = nt * 8 + 2 * j;
        int q = q0w + r4;
        Ob[d * 133 + q] = CO[nt][0] * li0;
        Ob[(d + 1) * 133 + q] = CO[nt][1] * li0;
        Ob[d * 133 + q + 8] = CO[nt][2] * li1;
        Ob[(d + 1) * 133 + q + 8] = CO[nt][3] * li1;
    }
    __syncthreads();
#pragma unroll
    for (int i = 0; i < 32; ++i) {
        int q = t & 127, d = (t >> 7) + 2 * i;
        size_t addr = ((size_t)(n * 1024 + h * 64 + d)) * 1024 + q0g + q;
        float r = tokens[addr] + Ob[d * 133 + q];
        g_t2[addr] = r;
        Ob[d * 133 + q] = r;
    }
    __syncthreads();
#pragma unroll
    for (int i = 0; i < 32; ++i) {
        int d = t & 63, l = (t >> 6) + 4 * i;
        g_t2T[((size_t)(n * 1024 + q0g + l)) * 1024 + h * 64 + d] = __float2half(Ob[d * 133 + l]);
    }
}

// ---------------- launch ----------------
extern "C" void kernel_launch(void* const* d_in, const int* in_sizes, int n_in,
                              void* d_out, int out_size)
{
    (void)in_sizes; (void)n_in; (void)out_size;
    const float* tokens = (const float*)d_in[0];
    const float* p[24];
    for (int i = 0; i < 24; ++i) p[i] = (const float*)d_in[1 + i];

    cudaFuncSetAttribute(qkv_tc, cudaFuncAttributeMaxDynamicSharedMemorySize, GEMM_SMEM);
    cudaFuncSetAttribute(fconv_tc, cudaFuncAttributeMaxDynamicSharedMemorySize, GEMM_SMEM);
    cudaFuncSetAttribute(attn_tc, cudaFuncAttributeMaxDynamicSharedMemorySize, ATTN_SMEM);

    int total_prep = 1024 * 1024 + 8 * 256 * 128 + 8 * 256 + 1024;
    prep_kernel<<<(total_prep + 255) / 256, 256>>>(
        p[0], p[1], p[2], p[3], p[4], p[5],
        p[6], p[7], p[8], p[9], p[10], p[11],
        p[12], p[13], p[14], p[15], p[16], p[17],
        p[18], p[19], p[20], p[21], p[22], p[23]);

    transpose_kernel<<<dim3(32, 32, 8), 256>>>(tokens);
    qkv_tc<<<dim3(8, 2, 64), 256, GEMM_SMEM>>>();
    attn_tc<<<dim3(8, 16, 8), 256, ATTN_SMEM>>>(tokens);
    fconv_tc<<<dim3(8, 8, 8), 256, GEMM_SMEM>>>((float*)d_out);
}